// round 2
// baseline (speedup 1.0000x reference)
#include <cuda_runtime.h>
#include <math.h>

#define CH    64
#define HW    4096
#define NB    4
#define CHW   (CH*HW)          // 262144
#define TOTAL (NB*CHW)         // 1048576

// Scratch (device globals: allocation-free per harness rules)
__device__ float g_yq[TOTAL];
__device__ float g_yk[TOTAL];
__device__ float g_gv[TOTAL];
__device__ float g_aff[4*CH];  // [0:64)=a_q, [64:128)=b_q, [128:192)=a_k, [192:256)=b_k

// ---------------------------------------------------------------------------
// Kernel 1: 1x1-conv projections y_q, y_k, and gated value gv=(h0+h1)*(Wv x+bv)
// Block: 256 threads, 128 positions. smem: Wq/Wk/Wv (3*16KB) + x tile (32KB)
// ---------------------------------------------------------------------------
__global__ __launch_bounds__(256)
void proj_kernel(const float* __restrict__ x,
                 const float* __restrict__ h0,
                 const float* __restrict__ h1,
                 const float* __restrict__ Wq, const float* __restrict__ bq,
                 const float* __restrict__ Wk, const float* __restrict__ bk,
                 const float* __restrict__ Wv, const float* __restrict__ bv) {
    extern __shared__ float sm[];
    float* sWq = sm;            // 4096
    float* sWk = sm + 4096;
    float* sWv = sm + 8192;
    float* xs  = sm + 12288;    // [64][128]

    int tid = threadIdx.x;
    for (int i = tid; i < 4096; i += 256) {
        sWq[i] = Wq[i]; sWk[i] = Wk[i]; sWv[i] = Wv[i];
    }
    int P0 = blockIdx.x * 128;          // flattened n*HW position
    int n  = P0 >> 12;
    int p0 = P0 & (HW - 1);
    const float* xb = x + (size_t)n*CHW + p0;
    for (int i = tid; i < 64*128; i += 256) {
        int c = i >> 7, pp = i & 127;
        xs[c*128 + pp] = xb[(size_t)c*HW + pp];
    }
    __syncthreads();

    int ty = tid >> 4, tx = tid & 15;   // 16x16 thread grid
    float aq[4][8], ak[4][8], av[4][8];
    #pragma unroll
    for (int io = 0; io < 4; io++) {
        int o = ty + 16*io;
        float bqv = bq[o], bkv = bk[o], bvv = bv[o];
        #pragma unroll
        for (int ip = 0; ip < 8; ip++) { aq[io][ip]=bqv; ak[io][ip]=bkv; av[io][ip]=bvv; }
    }
    for (int c = 0; c < 64; c++) {
        float xv[8];
        #pragma unroll
        for (int ip = 0; ip < 8; ip++) xv[ip] = xs[c*128 + tx + 16*ip];
        #pragma unroll
        for (int io = 0; io < 4; io++) {
            int o = ty + 16*io;
            float wq = sWq[o*64+c], wk = sWk[o*64+c], wv = sWv[o*64+c];
            #pragma unroll
            for (int ip = 0; ip < 8; ip++) {
                aq[io][ip] += wq*xv[ip];
                ak[io][ip] += wk*xv[ip];
                av[io][ip] += wv*xv[ip];
            }
        }
    }
    size_t base = (size_t)n*CHW + p0;
    #pragma unroll
    for (int io = 0; io < 4; io++) {
        int o = ty + 16*io;
        #pragma unroll
        for (int ip = 0; ip < 8; ip++) {
            int p = tx + 16*ip;
            size_t idx = base + (size_t)o*HW + p;
            g_yq[idx] = aq[io][ip];
            g_yk[idx] = ak[io][ip];
            g_gv[idx] = (h0[idx] + h1[idx]) * av[io][ip];
        }
    }
}

// ---------------------------------------------------------------------------
// Kernel 2: per-channel batch-norm stats -> affine coefs (a*y + b, then relu)
// blockIdx.x in [0,128): low 6 bits = channel, bit 6 = which tensor (0=q,1=k)
// ---------------------------------------------------------------------------
__global__ __launch_bounds__(256)
void stats_kernel(const float* __restrict__ gq, const float* __restrict__ betaq,
                  const float* __restrict__ gk, const float* __restrict__ betak) {
    int ch    = blockIdx.x & 63;
    int which = blockIdx.x >> 6;
    const float* y = which ? g_yk : g_yq;
    int tid = threadIdx.x;
    float s = 0.f, sq = 0.f;
    for (int n = 0; n < NB; n++) {
        const float* row = y + (size_t)n*CHW + (size_t)ch*HW;
        for (int p = tid; p < HW; p += 256) {
            float v = row[p];
            s += v; sq += v*v;
        }
    }
    __shared__ float rs[256], rq[256];
    rs[tid] = s; rq[tid] = sq;
    __syncthreads();
    for (int st = 128; st > 0; st >>= 1) {
        if (tid < st) { rs[tid] += rs[tid+st]; rq[tid] += rq[tid+st]; }
        __syncthreads();
    }
    if (tid == 0) {
        const float invn = 1.0f / (NB * HW);
        float mean = rs[0] * invn;
        float var  = rq[0] * invn - mean*mean;
        float g = which ? gk[ch]    : gq[ch];
        float b = which ? betak[ch] : betaq[ch];
        float a = g * rsqrtf(var + 1e-5f);
        g_aff[which*128 + ch]      = a;
        g_aff[which*128 + 64 + ch] = b - mean*a;
    }
}

// ---------------------------------------------------------------------------
// Kernel 3: flash-style attention. Block = (batch n, 64-query tile).
// Streams 64 key-tiles of 64 keys; online softmax; gated-V accumulation.
// smem: Qs[64][64] Ks[64][64] Gs[64][65] Ss[64][65]  (~66 KB)
// ---------------------------------------------------------------------------
__global__ __launch_bounds__(256)
void attn_kernel(float* __restrict__ out) {
    extern __shared__ float sm[];
    float* Qs = sm;              // [c][q]   4096
    float* Ks = sm + 4096;       // [c][k]   4096
    float* Gs = sm + 8192;       // [c][k]   64*65 padded
    float* Ss = sm + 12352;      // [q][k]   64*65 padded

    int tid = threadIdx.x;
    int n   = blockIdx.y;
    int q0  = blockIdx.x * 64;
    size_t nb = (size_t)n * CHW;

    // load Q tile with BN-affine + relu
    for (int i = tid; i < 4096; i += 256) {
        int c = i >> 6, qq = i & 63;
        float v = g_yq[nb + (size_t)c*HW + q0 + qq];
        Qs[c*64 + qq] = fmaxf(0.f, g_aff[c]*v + g_aff[64 + c]);
    }

    float outv[16];
    #pragma unroll
    for (int i = 0; i < 16; i++) outv[i] = 0.f;
    float m = -1e30f, l = 0.f;

    int ty = tid >> 4, tx = tid & 15;   // score-phase mapping
    int qr = tid >> 2, j  = tid & 3;    // softmax/accum mapping

    for (int kt = 0; kt < 64; kt++) {
        int k0 = kt * 64;
        __syncthreads();  // prior accum done (also publishes Qs on iter 0)
        for (int i = tid; i < 4096; i += 256) {
            int c = i >> 6, kk = i & 63;
            size_t gidx = nb + (size_t)c*HW + k0 + kk;
            float v = g_yk[gidx];
            Ks[c*64 + kk] = fmaxf(0.f, g_aff[128 + c]*v + g_aff[192 + c]);
            Gs[c*65 + kk] = g_gv[gidx];
        }
        __syncthreads();

        // scores: 4q x 4k register tile per thread
        float s[4][4];
        #pragma unroll
        for (int iq = 0; iq < 4; iq++)
            #pragma unroll
            for (int ik = 0; ik < 4; ik++) s[iq][ik] = 0.f;
        for (int c = 0; c < 64; c++) {
            float qv[4], kv[4];
            #pragma unroll
            for (int iq = 0; iq < 4; iq++) qv[iq] = Qs[c*64 + ty + 16*iq];
            #pragma unroll
            for (int ik = 0; ik < 4; ik++) kv[ik] = Ks[c*64 + tx + 16*ik];
            #pragma unroll
            for (int iq = 0; iq < 4; iq++)
                #pragma unroll
                for (int ik = 0; ik < 4; ik++) s[iq][ik] += qv[iq]*kv[ik];
        }
        #pragma unroll
        for (int iq = 0; iq < 4; iq++)
            #pragma unroll
            for (int ik = 0; ik < 4; ik++)
                Ss[(ty + 16*iq)*65 + tx + 16*ik] = s[iq][ik];
        __syncthreads();

        // online softmax: 4 threads per query row; each owns 16 key-entries
        float ev[16];
        float tmax = -1e30f;
        #pragma unroll
        for (int kk = 0; kk < 16; kk++) {
            float v = Ss[qr*65 + j*16 + kk];
            ev[kk] = v;
            tmax = fmaxf(tmax, v);
        }
        tmax = fmaxf(tmax, __shfl_xor_sync(0xffffffffu, tmax, 1));
        tmax = fmaxf(tmax, __shfl_xor_sync(0xffffffffu, tmax, 2));
        float mnew  = fmaxf(m, tmax);
        float scale = __expf(m - mnew);
        float lsum  = 0.f;
        #pragma unroll
        for (int kk = 0; kk < 16; kk++) {
            float e = __expf(ev[kk] - mnew);
            ev[kk] = e;
            lsum += e;
        }
        lsum += __shfl_xor_sync(0xffffffffu, lsum, 1);
        lsum += __shfl_xor_sync(0xffffffffu, lsum, 2);
        l = l*scale + lsum;
        m = mnew;
        #pragma unroll
        for (int i = 0; i < 16; i++) outv[i] *= scale;
        #pragma unroll
        for (int kk = 0; kk < 16; kk++) Ss[qr*65 + j*16 + kk] = ev[kk];
        __syncwarp();  // row's 4 lanes share a warp: publish P

        // accumulate: outv[c] += P[qr][k] * gv[c][k]
        for (int k = 0; k < 64; k++) {
            float p = Ss[qr*65 + k];
            #pragma unroll
            for (int cc = 0; cc < 16; cc++)
                outv[cc] += p * Gs[(j*16 + cc)*65 + k];
        }
    }

    float inv = 1.0f / l;
    #pragma unroll
    for (int cc = 0; cc < 16; cc++)
        out[nb + (size_t)(j*16 + cc)*HW + q0 + qr] = outv[cc] * inv;
}

// ---------------------------------------------------------------------------
extern "C" void kernel_launch(void* const* d_in, const int* in_sizes, int n_in,
                              void* d_out, int out_size) {
    const float* x     = (const float*)d_in[0];
    const float* h0    = (const float*)d_in[1];
    const float* h1    = (const float*)d_in[2];
    const float* Wq    = (const float*)d_in[3];
    const float* bq    = (const float*)d_in[4];
    const float* gq    = (const float*)d_in[5];
    const float* betaq = (const float*)d_in[6];
    const float* Wk    = (const float*)d_in[7];
    const float* bk    = (const float*)d_in[8];
    const float* gk    = (const float*)d_in[9];
    const float* betak = (const float*)d_in[10];
    const float* Wv    = (const float*)d_in[11];
    const float* bv    = (const float*)d_in[12];
    float* out = (float*)d_out;

    const int proj_smem = 20480 * 4;   // 80 KB
    const int attn_smem = 16512 * 4;   // ~64.5 KB
    cudaFuncSetAttribute(proj_kernel, cudaFuncAttributeMaxDynamicSharedMemorySize, proj_smem);
    cudaFuncSetAttribute(attn_kernel, cudaFuncAttributeMaxDynamicSharedMemorySize, attn_smem);

    proj_kernel<<<128, 256, proj_smem>>>(x, h0, h1, Wq, bq, Wk, bk, Wv, bv);
    stats_kernel<<<128, 256>>>(gq, betaq, gk, betak);
    attn_kernel<<<dim3(64, NB), 256, attn_smem>>>(out);
}

// round 3
// speedup vs baseline: 4.5820x; 4.5820x over previous
#include <cuda_runtime.h>
#include <math.h>

#define CH    64
#define HW    4096
#define NB    4
#define CHW   (CH*HW)          // 262144
#define TOTAL (NB*CHW)         // 1048576

typedef unsigned long long ull;

// Scratch (device globals: allocation-free per harness rules)
__device__ float g_yq[TOTAL];
__device__ float g_yk[TOTAL];
__device__ float g_gv[TOTAL];
__device__ float g_aff[4*CH];  // [0:64)=a_q, [64:128)=b_q, [128:192)=a_k, [192:256)=b_k

// ---------------- f32x2 helpers (packed dual-FMA; ptxas won't emit these) ---
__device__ __forceinline__ ull pk2(float x, float y) {
    ull r; asm("mov.b64 %0,{%1,%2};" : "=l"(r) : "f"(x), "f"(y)); return r;
}
__device__ __forceinline__ void upk2(ull v, float& x, float& y) {
    asm("mov.b64 {%0,%1},%2;" : "=f"(x), "=f"(y) : "l"(v));
}
__device__ __forceinline__ void fma2(ull& d, ull a, ull b) {
    asm("fma.rn.f32x2 %0,%1,%2,%0;" : "+l"(d) : "l"(a), "l"(b));
}
__device__ __forceinline__ void mul2i(ull& d, ull a) {
    asm("mul.rn.f32x2 %0,%1,%0;" : "+l"(d) : "l"(a));
}
__device__ __forceinline__ ull add2_(ull a, ull b) {
    ull r; asm("add.rn.f32x2 %0,%1,%2;" : "=l"(r) : "l"(a), "l"(b)); return r;
}
__device__ __forceinline__ ull mul2_(ull a, ull b) {
    ull r; asm("mul.rn.f32x2 %0,%1,%2;" : "=l"(r) : "l"(a), "l"(b)); return r;
}
__device__ __forceinline__ ull ld2(const float* p) {
    return *reinterpret_cast<const ull*>(p);
}

// ---------------------------------------------------------------------------
// Kernel 1: projections y_q, y_k and gated value gv = (h0+h1)*(Wv x + bv)
// grid 256 blocks x 64 positions, 256 threads, f32x2 inner loop.
// ---------------------------------------------------------------------------
__global__ __launch_bounds__(256)
void proj_kernel(const float* __restrict__ x,
                 const float* __restrict__ h0,
                 const float* __restrict__ h1,
                 const float* __restrict__ Wq, const float* __restrict__ bq,
                 const float* __restrict__ Wk, const float* __restrict__ bk,
                 const float* __restrict__ Wv, const float* __restrict__ bv) {
    extern __shared__ float sm[];
    float* sWq = sm;            // 4096
    float* sWk = sm + 4096;
    float* sWv = sm + 8192;
    float* xs  = sm + 12288;    // [64][64]

    int tid = threadIdx.x;
    for (int i = tid; i < 4096; i += 256) {
        sWq[i] = Wq[i]; sWk[i] = Wk[i]; sWv[i] = Wv[i];
    }
    int P0 = blockIdx.x * 64;
    int n  = P0 >> 12;
    int p0 = P0 & (HW - 1);
    const float* xb = x + (size_t)n*CHW + p0;
    for (int i = tid; i < 4096; i += 256) {
        int c = i >> 6, pp = i & 63;
        xs[c*64 + pp] = xb[(size_t)c*HW + pp];
    }
    __syncthreads();

    int ty = tid >> 4, tx = tid & 15;   // ty->output, tx->position pairs
    ull aq2[4][2], ak2[4][2], av2[4][2];
    #pragma unroll
    for (int io = 0; io < 4; io++) {
        int o = ty + 16*io;
        float bqo = bq[o], bko = bk[o], bvo = bv[o];
        aq2[io][0] = aq2[io][1] = pk2(bqo, bqo);
        ak2[io][0] = ak2[io][1] = pk2(bko, bko);
        av2[io][0] = av2[io][1] = pk2(bvo, bvo);
    }
    #pragma unroll 2
    for (int c = 0; c < 64; c++) {
        ull xv0 = ld2(&xs[c*64 + 2*tx]);
        ull xv1 = ld2(&xs[c*64 + 2*tx + 32]);
        #pragma unroll
        for (int io = 0; io < 4; io++) {
            int o = ty + 16*io;
            float wqs = sWq[o*64 + c], wks = sWk[o*64 + c], wvs = sWv[o*64 + c];
            ull wq = pk2(wqs, wqs), wk = pk2(wks, wks), wv = pk2(wvs, wvs);
            fma2(aq2[io][0], wq, xv0); fma2(aq2[io][1], wq, xv1);
            fma2(ak2[io][0], wk, xv0); fma2(ak2[io][1], wk, xv1);
            fma2(av2[io][0], wv, xv0); fma2(av2[io][1], wv, xv1);
        }
    }
    size_t base = (size_t)n*CHW + p0;
    #pragma unroll
    for (int io = 0; io < 4; io++) {
        int o = ty + 16*io;
        #pragma unroll
        for (int ip = 0; ip < 2; ip++) {
            size_t idx = base + (size_t)o*HW + 2*tx + 32*ip;
            *reinterpret_cast<ull*>(&g_yq[idx]) = aq2[io][ip];
            *reinterpret_cast<ull*>(&g_yk[idx]) = ak2[io][ip];
            ull h0p = *reinterpret_cast<const ull*>(&h0[idx]);
            ull h1p = *reinterpret_cast<const ull*>(&h1[idx]);
            *reinterpret_cast<ull*>(&g_gv[idx]) = mul2_(add2_(h0p, h1p), av2[io][ip]);
        }
    }
}

// ---------------------------------------------------------------------------
// Kernel 2: per-channel batch-norm stats -> affine coefs
// ---------------------------------------------------------------------------
__global__ __launch_bounds__(256)
void stats_kernel(const float* __restrict__ gq, const float* __restrict__ betaq,
                  const float* __restrict__ gk, const float* __restrict__ betak) {
    int ch    = blockIdx.x & 63;
    int which = blockIdx.x >> 6;
    const float* y = which ? g_yk : g_yq;
    int tid = threadIdx.x;
    float s = 0.f, sq = 0.f;
    for (int n = 0; n < NB; n++) {
        const float* row = y + (size_t)n*CHW + (size_t)ch*HW;
        for (int p = tid; p < HW; p += 256) {
            float v = row[p];
            s += v; sq += v*v;
        }
    }
    __shared__ float rs[256], rq[256];
    rs[tid] = s; rq[tid] = sq;
    __syncthreads();
    for (int st = 128; st > 0; st >>= 1) {
        if (tid < st) { rs[tid] += rs[tid+st]; rq[tid] += rq[tid+st]; }
        __syncthreads();
    }
    if (tid == 0) {
        const float invn = 1.0f / (NB * HW);
        float mean = rs[0] * invn;
        float var  = rq[0] * invn - mean*mean;
        float g = which ? gk[ch]    : gq[ch];
        float b = which ? betak[ch] : betaq[ch];
        float a = g * rsqrtf(var + 1e-5f);
        g_aff[which*128 + ch]      = a;
        g_aff[which*128 + 64 + ch] = b - mean*a;
    }
}

// ---------------------------------------------------------------------------
// Kernel 3: flash attention, Bq=128 queries/block, Bk=64 keys/tile, f32x2.
// grid (32, NB), 256 threads, ~100 KB smem.
// ---------------------------------------------------------------------------
#define BQ 128
#define BK 64

__global__ __launch_bounds__(256, 1)
void attn_kernel(float* __restrict__ out) {
    extern __shared__ float sm[];
    float* Qs  = sm;             // [c][q]  64x128           8192
    float* Ks  = sm + 8192;      // [c][k]  64x64            4096
    float* Gs  = sm + 12288;     // [c][k]  64x66 (padded)   4224
    float* Ss  = sm + 16512;     // [q][k] 128x66 (padded)   8448
    float* scl = sm + 24960;     // [q]    128  (scale, then 1/l)

    int tid = threadIdx.x;
    int n   = blockIdx.y;
    int q0  = blockIdx.x * BQ;
    size_t nb = (size_t)n * CHW;
    int ty = tid >> 4, tx = tid & 15;
    int qr = tid >> 1, j = tid & 1;       // softmax mapping: 2 threads/row

    // Q tile with BN-affine + relu
    for (int i = tid; i < 64*BQ; i += 256) {
        int c = i >> 7, q = i & 127;
        float v = g_yq[nb + (size_t)c*HW + q0 + q];
        Qs[c*128 + q] = fmaxf(0.f, g_aff[c]*v + g_aff[64 + c]);
    }

    // ctx accumulators: thread owns q = ty+16*iq (8), c = tx+16*ic (4),
    // each ull accumulates (even-k, odd-k) partial sums.
    ull outv[8][4];
    #pragma unroll
    for (int iq = 0; iq < 8; iq++)
        #pragma unroll
        for (int ic = 0; ic < 4; ic++) outv[iq][ic] = 0ull;
    float m = -1e30f, l = 0.f;

    for (int kt = 0; kt < 64; kt++) {
        int k0 = kt * BK;
        __syncthreads();   // prior accum done; publishes Qs on iter 0
        for (int i = tid; i < 64*BK; i += 256) {
            int c = i >> 6, kk = i & 63;
            size_t gi = nb + (size_t)c*HW + k0 + kk;
            Ks[c*64 + kk] = fmaxf(0.f, g_aff[128 + c]*g_yk[gi] + g_aff[192 + c]);
            Gs[c*66 + kk] = g_gv[gi];
        }
        __syncthreads();

        // ---- scores: thread = 4 q-pairs (q = 2ty+32*iq2 +{0,1}) x 4 k ----
        ull s2[4][4];
        #pragma unroll
        for (int iq = 0; iq < 4; iq++)
            #pragma unroll
            for (int ik = 0; ik < 4; ik++) s2[iq][ik] = 0ull;
        #pragma unroll 2
        for (int c = 0; c < 64; c++) {
            ull qp[4], kk2[4];
            #pragma unroll
            for (int iq = 0; iq < 4; iq++)
                qp[iq] = ld2(&Qs[c*128 + 2*ty + 32*iq]);
            #pragma unroll
            for (int ik = 0; ik < 4; ik++) {
                float kv = Ks[c*64 + tx + 16*ik];
                kk2[ik] = pk2(kv, kv);
            }
            #pragma unroll
            for (int iq = 0; iq < 4; iq++)
                #pragma unroll
                for (int ik = 0; ik < 4; ik++)
                    fma2(s2[iq][ik], qp[iq], kk2[ik]);
        }
        #pragma unroll
        for (int iq = 0; iq < 4; iq++) {
            int q = 2*ty + 32*iq;
            #pragma unroll
            for (int ik = 0; ik < 4; ik++) {
                float lo, hi; upk2(s2[iq][ik], lo, hi);
                Ss[q*66 + tx + 16*ik]     = lo;
                Ss[(q+1)*66 + tx + 16*ik] = hi;
            }
        }
        __syncthreads();

        // ---- online softmax: thread j handles 32 of 64 cols of row qr ----
        {
            float* row = Ss + qr*66 + j*32;
            float2 ev[16];
            float tmax = -1e30f;
            #pragma unroll
            for (int kk = 0; kk < 16; kk++) {
                ev[kk] = *reinterpret_cast<const float2*>(row + 2*kk);
                tmax = fmaxf(tmax, fmaxf(ev[kk].x, ev[kk].y));
            }
            tmax = fmaxf(tmax, __shfl_xor_sync(0xffffffffu, tmax, 1));
            float mnew = fmaxf(m, tmax);
            float sc   = __expf(m - mnew);
            float ls = 0.f;
            #pragma unroll
            for (int kk = 0; kk < 16; kk++) {
                float ex = __expf(ev[kk].x - mnew);
                float ey = __expf(ev[kk].y - mnew);
                ls += ex + ey;
                *reinterpret_cast<float2*>(row + 2*kk) = make_float2(ex, ey);
            }
            ls += __shfl_xor_sync(0xffffffffu, ls, 1);
            l = l*sc + ls;
            m = mnew;
            if (j == 0) scl[qr] = sc;
        }
        __syncthreads();

        // ---- accumulate ctx += P * G^T (register-tiled, k-paired) ----
        #pragma unroll
        for (int iq = 0; iq < 8; iq++) {
            float s = scl[ty + 16*iq];
            ull sp = pk2(s, s);
            #pragma unroll
            for (int ic = 0; ic < 4; ic++) mul2i(outv[iq][ic], sp);
        }
        #pragma unroll 4
        for (int kp = 0; kp < 32; kp++) {
            ull P2[8], G2[4];
            #pragma unroll
            for (int iq = 0; iq < 8; iq++)
                P2[iq] = ld2(&Ss[(ty + 16*iq)*66 + 2*kp]);
            #pragma unroll
            for (int ic = 0; ic < 4; ic++)
                G2[ic] = ld2(&Gs[(tx + 16*ic)*66 + 2*kp]);
            #pragma unroll
            for (int iq = 0; iq < 8; iq++)
                #pragma unroll
                for (int ic = 0; ic < 4; ic++)
                    fma2(outv[iq][ic], P2[iq], G2[ic]);
        }
    }

    // ---- finalize: 1/l, transpose through smem, coalesced store ----
    __syncthreads();
    if (j == 0) scl[qr] = 1.0f / l;
    __syncthreads();
    float* Os = Ss;   // reuse, pitch 129 (64*129 = 8256 <= 8448)
    #pragma unroll
    for (int iq = 0; iq < 8; iq++) {
        int q = ty + 16*iq;
        float inv = scl[q];
        #pragma unroll
        for (int ic = 0; ic < 4; ic++) {
            int c = tx + 16*ic;
            float lo, hi; upk2(outv[iq][ic], lo, hi);
            Os[c*129 + q] = (lo + hi) * inv;
        }
    }
    __syncthreads();
    for (int i = tid; i < 64*BQ; i += 256) {
        int c = i >> 7, q = i & 127;
        out[nb + (size_t)c*HW + q0 + q] = Os[c*129 + q];
    }
}

// ---------------------------------------------------------------------------
extern "C" void kernel_launch(void* const* d_in, const int* in_sizes, int n_in,
                              void* d_out, int out_size) {
    const float* x     = (const float*)d_in[0];
    const float* h0    = (const float*)d_in[1];
    const float* h1    = (const float*)d_in[2];
    const float* Wq    = (const float*)d_in[3];
    const float* bq    = (const float*)d_in[4];
    const float* gq    = (const float*)d_in[5];
    const float* betaq = (const float*)d_in[6];
    const float* Wk    = (const float*)d_in[7];
    const float* bk    = (const float*)d_in[8];
    const float* gk    = (const float*)d_in[9];
    const float* betak = (const float*)d_in[10];
    const float* Wv    = (const float*)d_in[11];
    const float* bv    = (const float*)d_in[12];
    float* out = (float*)d_out;

    const int proj_smem = 16384 * 4;   // 64 KB
    const int attn_smem = 25088 * 4;   // ~98 KB
    cudaFuncSetAttribute(proj_kernel, cudaFuncAttributeMaxDynamicSharedMemorySize, proj_smem);
    cudaFuncSetAttribute(attn_kernel, cudaFuncAttributeMaxDynamicSharedMemorySize, attn_smem);

    proj_kernel<<<256, 256, proj_smem>>>(x, h0, h1, Wq, bq, Wk, bk, Wv, bv);
    stats_kernel<<<128, 256>>>(gq, betaq, gk, betak);
    attn_kernel<<<dim3(HW/BQ, NB), 256, attn_smem>>>(out);
}